// round 2
// baseline (speedup 1.0000x reference)
#include <cuda_runtime.h>

#define IMG_D 224
#define HW (IMG_D * IMG_D)
#define NBATCH 64

#define R_TILE 16                    // output rows per block
#define HALO 4                       // staged halo rows each side
#define WIN_MAX (R_TILE + 2 * HALO)  // 24 rows staged
#define TILES_PER_IMG (IMG_D / R_TILE)  // 14
#define TPB 256
#define PX_PER_BLK (R_TILE * IMG_D)      // 3584
#define PX_PER_THREAD (PX_PER_BLK / TPB) // 14

// Block = (batch n, 16-row tile). For each (channel, image) pair:
//   1. stage a 24-row window of the image plane into smem (coalesced float4)
//   2. bilinear-gather the 4 corners from smem (LDS, conflict-free)
//      with a rare global-load fallback when a corner row falls outside
//      the staged window (|C| > HALO or near-edge clipping)
// Accumulate masked im1(q+C) + im2(q-C) per channel, store coalesced.

__global__ __launch_bounds__(TPB)
void view_morph_tiled_kernel(
    const float* __restrict__ im1,
    const float* __restrict__ im2,
    const float* __restrict__ C,
    const float* __restrict__ M1,
    const float* __restrict__ M2,
    float* __restrict__ out)
{
    __shared__ float s_plane[WIN_MAX * IMG_D];  // 21504 B

    int blk = blockIdx.x;
    int n = blk / TILES_PER_IMG;
    int tile = blk - n * TILES_PER_IMG;
    int r0 = tile * R_TILE;

    int win_lo = max(0, r0 - HALO);
    int win_hi = min(IMG_D - 1, r0 + R_TILE - 1 + HALO);
    int win_cnt = win_hi - win_lo + 1;

    const float* Cn  = C  + (size_t)n * 2 * HW;
    const float* M1n = M1 + (size_t)n * HW;
    const float* M2n = M2 + (size_t)n * HW;
    int pix_base = r0 * IMG_D;

    for (int ch = 0; ch < 3; ch++) {
        float acc[PX_PER_THREAD];
        #pragma unroll
        for (int k = 0; k < PX_PER_THREAD; k++) acc[k] = 0.0f;

        for (int img = 0; img < 2; img++) {
            const float* plane =
                (img == 0 ? im1 : im2) + (size_t)(n * 3 + ch) * HW;

            __syncthreads();  // previous plane's reads done before overwrite
            {
                int tot4 = (win_cnt * IMG_D) >> 2;
                const float4* src = (const float4*)(plane + win_lo * IMG_D);
                float4* dst = (float4*)s_plane;
                for (int i = threadIdx.x; i < tot4; i += TPB)
                    dst[i] = __ldg(src + i);
            }
            __syncthreads();

            float sgn = (img == 0) ? 1.0f : -1.0f;
            const float* Mn = (img == 0) ? M1n : M2n;

            #pragma unroll
            for (int k = 0; k < PX_PER_THREAD; k++) {
                int p_local = threadIdx.x + k * TPB;
                int rl = p_local / IMG_D;
                int col = p_local - rl * IMG_D;
                int p = pix_base + p_local;

                float cx = __ldg(Cn + p);
                float cy = __ldg(Cn + HW + p);
                float m  = __ldg(Mn + p);

                float x = (float)(r0 + rl) + sgn * cx;
                float y = (float)col + sgn * cy;
                x = fminf(fmaxf(x, 0.001f), (float)IMG_D - 1.001f);
                y = fminf(fmaxf(y, 0.001f), (float)IMG_D - 1.001f);

                float xf = floorf(x), xc = ceilf(x);
                float yf = floorf(y), yc = ceilf(y);
                float wxf = 1.0f - (x - xf);
                float wxc = 1.0f - (xc - x);
                float wyf = 1.0f - (y - yf);
                float wyc = 1.0f - (yc - y);

                int ixf = (int)xf, ixc = (int)xc;
                int iyf = (int)yf, iyc = (int)yc;

                int rf = ixf - win_lo;
                int rc = ixc - win_lo;

                float v00, v01, v10, v11;
                if (rf >= 0 && rf < win_cnt) {
                    v00 = s_plane[rf * IMG_D + iyf];
                    v01 = s_plane[rf * IMG_D + iyc];
                } else {
                    v00 = __ldg(plane + ixf * IMG_D + iyf);
                    v01 = __ldg(plane + ixf * IMG_D + iyc);
                }
                if (rc >= 0 && rc < win_cnt) {
                    v10 = s_plane[rc * IMG_D + iyf];
                    v11 = s_plane[rc * IMG_D + iyc];
                } else {
                    v10 = __ldg(plane + ixc * IMG_D + iyf);
                    v11 = __ldg(plane + ixc * IMG_D + iyc);
                }

                float v = wxf * (wyf * v00 + wyc * v01)
                        + wxc * (wyf * v10 + wyc * v11);
                acc[k] += m * v;
            }
        }

        float* outp = out + (size_t)(n * 3 + ch) * HW + pix_base;
        #pragma unroll
        for (int k = 0; k < PX_PER_THREAD; k++)
            outp[threadIdx.x + k * TPB] = acc[k];
    }
}

extern "C" void kernel_launch(void* const* d_in, const int* in_sizes, int n_in,
                              void* d_out, int out_size)
{
    const float* im1 = (const float*)d_in[0];
    const float* im2 = (const float*)d_in[1];
    const float* C   = (const float*)d_in[2];
    const float* M1  = (const float*)d_in[3];
    const float* M2  = (const float*)d_in[4];
    float* out = (float*)d_out;

    int blocks = NBATCH * TILES_PER_IMG;  // 896
    view_morph_tiled_kernel<<<blocks, TPB>>>(im1, im2, C, M1, M2, out);
}

// round 3
// speedup vs baseline: 1.2342x; 1.2342x over previous
#include <cuda_runtime.h>

#define IMG_D 224
#define HW (IMG_D * IMG_D)
#define NBATCH 64

#define R_TILE 8                      // output rows per block
#define HALO 4                        // halo rows each side
#define WMAX (R_TILE + 2 * HALO)      // 16 rows staged max
#define TILES_PER_IMG (IMG_D / R_TILE)  // 28
#define TPB IMG_D                     // 224: thread == column, no division

// Block = (batch n, 8-row band). Per image: stage a <=16-row window of all
// 3 channel planes into smem (43KB, coalesced float4), then bilinear-gather
// the 4 corners per (pixel, channel) as conflict-free LDS (lanes are
// consecutive columns +- N(0,1) jitter). Out-of-window corner rows (rare,
// |C|>HALO or edge clip) take a predicated global fallback. Accumulate
// masked im1(q+C)+im2(q-C) across both images in registers, store once.

__global__ __launch_bounds__(TPB)
void view_morph3_kernel(
    const float* __restrict__ im1,
    const float* __restrict__ im2,
    const float* __restrict__ C,
    const float* __restrict__ M1,
    const float* __restrict__ M2,
    float* __restrict__ out)
{
    __shared__ float sp[3][WMAX * IMG_D];   // 3*16*224*4 = 43008 B

    int blk = blockIdx.x;
    int n = blk / TILES_PER_IMG;
    int tile = blk - n * TILES_PER_IMG;
    int r0 = tile * R_TILE;

    int wl = max(0, r0 - HALO);
    int wh = min(IMG_D - 1, r0 + R_TILE - 1 + HALO);
    int wc = wh - wl + 1;

    int col = threadIdx.x;

    const float* Cn  = C  + (size_t)n * 2 * HW;
    const float* M1n = M1 + (size_t)n * HW;
    const float* M2n = M2 + (size_t)n * HW;

    float acc[3][R_TILE];
    #pragma unroll
    for (int c = 0; c < 3; c++)
        #pragma unroll
        for (int k = 0; k < R_TILE; k++) acc[c][k] = 0.0f;

    #pragma unroll
    for (int img = 0; img < 2; img++) {
        const float* pl = (img == 0 ? im1 : im2) + (size_t)n * 3 * HW;

        __syncthreads();   // previous image's smem reads complete
        {
            int tot4 = wc * (IMG_D / 4);   // float4s per plane
            #pragma unroll
            for (int c = 0; c < 3; c++) {
                const float4* src = (const float4*)(pl + c * HW + wl * IMG_D);
                float4* dst = (float4*)sp[c];
                for (int i = threadIdx.x; i < tot4; i += TPB)
                    dst[i] = __ldg(src + i);
            }
        }
        __syncthreads();

        float sgn = (img == 0) ? 1.0f : -1.0f;
        const float* Mn = (img == 0) ? M1n : M2n;

        #pragma unroll
        for (int k = 0; k < R_TILE; k++) {
            int r = r0 + k;
            int p = r * IMG_D + col;

            float cx = __ldg(Cn + p);
            float cy = __ldg(Cn + HW + p);
            float m  = __ldg(Mn + p);

            float x = (float)r   + sgn * cx;
            float y = (float)col + sgn * cy;
            x = fminf(fmaxf(x, 0.001f), (float)IMG_D - 1.001f);
            y = fminf(fmaxf(y, 0.001f), (float)IMG_D - 1.001f);

            float xf = floorf(x), xc = ceilf(x);
            float yf = floorf(y), yc = ceilf(y);
            float wxf = 1.0f - (x - xf);
            float wxc = 1.0f - (xc - x);
            float wyf = 1.0f - (y - yf);
            float wyc = 1.0f - (yc - y);

            int ixf = (int)xf, ixc = (int)xc;
            int iyf = (int)yf, iyc = (int)yc;

            int rf = ixf - wl;
            int rc = ixc - wl;
            bool inf = (unsigned)rf < (unsigned)wc;
            bool inc = (unsigned)rc < (unsigned)wc;

            int sf = rf * IMG_D;        // smem row offsets
            int sc = rc * IMG_D;
            int gf = ixf * IMG_D;       // global fallback row offsets
            int gc = ixc * IMG_D;

            #pragma unroll
            for (int c = 0; c < 3; c++) {
                float v00, v01, v10, v11;
                if (inf) {
                    v00 = sp[c][sf + iyf];
                    v01 = sp[c][sf + iyc];
                } else {
                    const float* b = pl + c * HW + gf;
                    v00 = __ldg(b + iyf);
                    v01 = __ldg(b + iyc);
                }
                if (inc) {
                    v10 = sp[c][sc + iyf];
                    v11 = sp[c][sc + iyc];
                } else {
                    const float* b = pl + c * HW + gc;
                    v10 = __ldg(b + iyf);
                    v11 = __ldg(b + iyc);
                }
                float v = wxf * (wyf * v00 + wyc * v01)
                        + wxc * (wyf * v10 + wyc * v11);
                acc[c][k] += m * v;
            }
        }
    }

    float* outn = out + (size_t)n * 3 * HW;
    #pragma unroll
    for (int c = 0; c < 3; c++) {
        float* op = outn + c * HW + r0 * IMG_D + col;
        #pragma unroll
        for (int k = 0; k < R_TILE; k++)
            op[k * IMG_D] = acc[c][k];
    }
}

extern "C" void kernel_launch(void* const* d_in, const int* in_sizes, int n_in,
                              void* d_out, int out_size)
{
    const float* im1 = (const float*)d_in[0];
    const float* im2 = (const float*)d_in[1];
    const float* C   = (const float*)d_in[2];
    const float* M1  = (const float*)d_in[3];
    const float* M2  = (const float*)d_in[4];
    float* out = (float*)d_out;

    int blocks = NBATCH * TILES_PER_IMG;  // 1792
    view_morph3_kernel<<<blocks, TPB>>>(im1, im2, C, M1, M2, out);
}

// round 4
// speedup vs baseline: 1.4488x; 1.1739x over previous
#include <cuda_runtime.h>
#include <cstdint>

#define IMG_D 224
#define HW (IMG_D * IMG_D)
#define NBATCH 64

#define R_TILE 8
#define HALO 4
#define WMAX (R_TILE + 2 * HALO)        // 16 rows staged
#define TILES_PER_IMG (IMG_D / R_TILE)  // 28
#define TPB IMG_D                       // 224: thread == column

__device__ __forceinline__ void cp_async16(uint32_t saddr, const void* g) {
    asm volatile("cp.async.cg.shared.global [%0], [%1], 16;\n"
                 :: "r"(saddr), "l"(g));
}

__device__ __forceinline__ float bilerp(
    const float* __restrict__ sm,    // staged window (row 0 == global row wl)
    const float* __restrict__ gpl,   // global plane fallback
    float x, float y, int wl, int wc)
{
    x = fminf(fmaxf(x, 0.001f), (float)IMG_D - 1.001f);
    y = fminf(fmaxf(y, 0.001f), (float)IMG_D - 1.001f);

    float xf = floorf(x), xc = ceilf(x);
    float yf = floorf(y), yc = ceilf(y);
    float wxf = 1.0f - (x - xf);
    float wxc = 1.0f - (xc - x);
    float wyf = 1.0f - (y - yf);
    float wyc = 1.0f - (yc - y);

    int ixf = (int)xf, ixc = (int)xc;
    int iyf = (int)yf, iyc = (int)yc;

    int rf = ixf - wl;
    int rc = ixc - wl;

    float v00, v01, v10, v11;
    if ((unsigned)rf < (unsigned)wc) {
        v00 = sm[rf * IMG_D + iyf];
        v01 = sm[rf * IMG_D + iyc];
    } else {
        v00 = __ldg(gpl + ixf * IMG_D + iyf);
        v01 = __ldg(gpl + ixf * IMG_D + iyc);
    }
    if ((unsigned)rc < (unsigned)wc) {
        v10 = sm[rc * IMG_D + iyf];
        v11 = sm[rc * IMG_D + iyc];
    } else {
        v10 = __ldg(gpl + ixc * IMG_D + iyf);
        v11 = __ldg(gpl + ixc * IMG_D + iyc);
    }
    return wxf * (wyf * v00 + wyc * v01) + wxc * (wyf * v10 + wyc * v11);
}

// Block = (n, 8-row tile, channel). ch varies fastest in blockIdx so the
// three channel-blocks of one (n,tile) run concurrently and share C/M via L2.
// One cp.async stage of two plane windows + ONE barrier, then pure
// LDS-gather compute (conflict-free: lanes are consecutive cols +- jitter).
__global__ __launch_bounds__(TPB, 5)
void view_morph4_kernel(
    const float* __restrict__ im1,
    const float* __restrict__ im2,
    const float* __restrict__ C,
    const float* __restrict__ M1,
    const float* __restrict__ M2,
    float* __restrict__ out)
{
    __shared__ float sp[2][WMAX * IMG_D];   // 28672 B

    int blk = blockIdx.x;
    int ch = blk % 3;
    int t2 = blk / 3;
    int tile = t2 % TILES_PER_IMG;
    int n = t2 / TILES_PER_IMG;
    int r0 = tile * R_TILE;

    int wl = max(0, r0 - HALO);
    int wh = min(IMG_D - 1, r0 + R_TILE - 1 + HALO);
    int wc = wh - wl + 1;

    int col = threadIdx.x;

    const float* p1 = im1 + (size_t)(n * 3 + ch) * HW;
    const float* p2 = im2 + (size_t)(n * 3 + ch) * HW;

    // ── stage both plane windows via cp.async ──
    {
        int tot4 = wc * (IMG_D / 4);
        const float4* s1 = (const float4*)(p1 + wl * IMG_D);
        const float4* s2 = (const float4*)(p2 + wl * IMG_D);
        uint32_t d1 = (uint32_t)__cvta_generic_to_shared(&sp[0][0]);
        uint32_t d2 = (uint32_t)__cvta_generic_to_shared(&sp[1][0]);
        for (int i = threadIdx.x; i < tot4; i += TPB) {
            cp_async16(d1 + i * 16, s1 + i);
            cp_async16(d2 + i * 16, s2 + i);
        }
        asm volatile("cp.async.commit_group;\n");
        asm volatile("cp.async.wait_group 0;\n" ::: "memory");
    }
    __syncthreads();

    const float* Cn  = C  + (size_t)n * 2 * HW;
    const float* M1n = M1 + (size_t)n * HW;
    const float* M2n = M2 + (size_t)n * HW;

    float acc[R_TILE];

    #pragma unroll
    for (int k = 0; k < R_TILE; k++) {
        int r = r0 + k;
        int p = r * IMG_D + col;

        float cx = __ldg(Cn + p);
        float cy = __ldg(Cn + HW + p);
        float m1 = __ldg(M1n + p);
        float m2 = __ldg(M2n + p);

        float fr = (float)r, fc = (float)col;

        float a  = m1 * bilerp(sp[0], p1, fr + cx, fc + cy, wl, wc);
        a       += m2 * bilerp(sp[1], p2, fr - cx, fc - cy, wl, wc);
        acc[k] = a;
    }

    float* op = out + (size_t)(n * 3 + ch) * HW + r0 * IMG_D + col;
    #pragma unroll
    for (int k = 0; k < R_TILE; k++)
        op[k * IMG_D] = acc[k];
}

extern "C" void kernel_launch(void* const* d_in, const int* in_sizes, int n_in,
                              void* d_out, int out_size)
{
    const float* im1 = (const float*)d_in[0];
    const float* im2 = (const float*)d_in[1];
    const float* C   = (const float*)d_in[2];
    const float* M1  = (const float*)d_in[3];
    const float* M2  = (const float*)d_in[4];
    float* out = (float*)d_out;

    int blocks = NBATCH * TILES_PER_IMG * 3;  // 5376
    view_morph4_kernel<<<blocks, TPB>>>(im1, im2, C, M1, M2, out);
}

// round 5
// speedup vs baseline: 2.2626x; 1.5618x over previous
#include <cuda_runtime.h>
#include <cstdint>

#define IMG_D 224
#define HW (IMG_D * IMG_D)
#define NBATCH 64

#define R_TILE 8
#define HALO 4
#define WMAX (R_TILE + 2 * HALO)        // 16 rows staged
#define TILES_PER_IMG (IMG_D / R_TILE)  // 28
#define TPB 448                         // 2 sub-rows x 224 cols
#define ROWSUB (TPB / IMG_D)            // 2
#define PXT (R_TILE / ROWSUB)           // 4 pixels per thread
#define PLANE_W (WMAX * IMG_D)          // 3584 floats per staged plane
#define SMEM_BYTES (6 * PLANE_W * 4)    // 86016 B (dynamic)

__device__ __forceinline__ void cp_async16(uint32_t saddr, const void* g) {
    asm volatile("cp.async.cg.shared.global [%0], [%1], 16;\n"
                 :: "r"(saddr), "l"(g));
}

// Block = (n, 8-row tile). Stage all 6 channel-plane windows (im1,im2 x 3ch,
// 16 rows w/ 4-row halo) via one cp.async burst + ONE barrier. Coordinate /
// weight math once per (pixel, image); gathers are conflict-free LDS (row
// stride 224 == 0 mod 32 banks -> bank = column; lanes = distinct columns).
// Rare out-of-window corner (|C|>4 or edge clip, P~6e-5) -> all-global path.
__global__ __launch_bounds__(TPB)
void view_morph5_kernel(
    const float* __restrict__ im1,
    const float* __restrict__ im2,
    const float* __restrict__ C,
    const float* __restrict__ M1,
    const float* __restrict__ M2,
    float* __restrict__ out)
{
    extern __shared__ float sp[];   // [img*3 + ch] planes of PLANE_W floats

    int blk = blockIdx.x;
    int n = blk / TILES_PER_IMG;
    int tile = blk - n * TILES_PER_IMG;
    int r0 = tile * R_TILE;

    int wl = max(0, r0 - HALO);
    int wh = min(IMG_D - 1, r0 + R_TILE - 1 + HALO);
    int wc = wh - wl + 1;

    int tid = threadIdx.x;
    int col = tid % IMG_D;
    int rsub = tid / IMG_D;

    const float* b1 = im1 + (size_t)n * 3 * HW;   // channel-0 plane of im1[n]
    const float* b2 = im2 + (size_t)n * 3 * HW;

    // ── prefetch C/M for this thread's 4 pixels (hidden under staging) ──
    const float* Cn  = C  + (size_t)n * 2 * HW;
    const float* M1n = M1 + (size_t)n * HW;
    const float* M2n = M2 + (size_t)n * HW;

    float cx[PXT], cy[PXT], m1v[PXT], m2v[PXT];
    #pragma unroll
    for (int k = 0; k < PXT; k++) {
        int r = r0 + rsub + k * ROWSUB;
        int p = r * IMG_D + col;
        cx[k]  = __ldg(Cn + p);
        cy[k]  = __ldg(Cn + HW + p);
        m1v[k] = __ldg(M1n + p);
        m2v[k] = __ldg(M2n + p);
    }

    // ── stage 6 contiguous plane windows ──
    {
        int tot4 = wc * (IMG_D / 4);             // float4s per plane (<=896)
        uint32_t sb = (uint32_t)__cvta_generic_to_shared(sp);
        const float4* g0 = (const float4*)(b1 + 0 * HW + wl * IMG_D);
        const float4* g1 = (const float4*)(b1 + 1 * HW + wl * IMG_D);
        const float4* g2 = (const float4*)(b1 + 2 * HW + wl * IMG_D);
        const float4* g3 = (const float4*)(b2 + 0 * HW + wl * IMG_D);
        const float4* g4 = (const float4*)(b2 + 1 * HW + wl * IMG_D);
        const float4* g5 = (const float4*)(b2 + 2 * HW + wl * IMG_D);
        for (int i = tid; i < tot4; i += TPB) {
            uint32_t so = sb + i * 16;
            cp_async16(so + 0 * PLANE_W * 4, g0 + i);
            cp_async16(so + 1 * PLANE_W * 4, g1 + i);
            cp_async16(so + 2 * PLANE_W * 4, g2 + i);
            cp_async16(so + 3 * PLANE_W * 4, g3 + i);
            cp_async16(so + 4 * PLANE_W * 4, g4 + i);
            cp_async16(so + 5 * PLANE_W * 4, g5 + i);
        }
        asm volatile("cp.async.commit_group;\n");
        asm volatile("cp.async.wait_group 0;\n" ::: "memory");
    }
    __syncthreads();

    float acc[3][PXT];
    #pragma unroll
    for (int c = 0; c < 3; c++)
        #pragma unroll
        for (int k = 0; k < PXT; k++) acc[c][k] = 0.0f;

    #pragma unroll
    for (int k = 0; k < PXT; k++) {
        int r = r0 + rsub + k * ROWSUB;
        float fr = (float)r, fc = (float)col;

        #pragma unroll
        for (int img = 0; img < 2; img++) {
            float s = (img == 0) ? 1.0f : -1.0f;
            float m = (img == 0) ? m1v[k] : m2v[k];
            const float* gb = (img == 0) ? b1 : b2;
            const float* spb = sp + img * 3 * PLANE_W;

            float x = fr + s * cx[k];
            float y = fc + s * cy[k];
            x = fminf(fmaxf(x, 0.001f), (float)IMG_D - 1.001f);
            y = fminf(fmaxf(y, 0.001f), (float)IMG_D - 1.001f);

            int ixf = __float2int_rd(x);
            int ixc = __float2int_ru(x);
            int iyf = __float2int_rd(y);
            int iyc = __float2int_ru(y);

            float wxf = 1.0f - (x - (float)ixf);
            float wxc = 1.0f - ((float)ixc - x);
            float wyf = 1.0f - (y - (float)iyf);
            float wyc = 1.0f - ((float)iyc - y);

            float w00 = wxf * wyf;
            float w10 = wxc * wyf;
            float w01 = wxf * wyc;
            float w11 = wxc * wyc;

            int rf = ixf - wl;
            int rc = ixc - wl;
            bool ok = ((unsigned)rf < (unsigned)wc) &
                      ((unsigned)rc < (unsigned)wc);

            float v00[3], v10[3], v01[3], v11[3];
            if (ok) {
                const float* smf = spb + rf * IMG_D;
                const float* smc = spb + rc * IMG_D;
                #pragma unroll
                for (int c = 0; c < 3; c++) {
                    v00[c] = smf[c * PLANE_W + iyf];
                    v01[c] = smf[c * PLANE_W + iyc];
                    v10[c] = smc[c * PLANE_W + iyf];
                    v11[c] = smc[c * PLANE_W + iyc];
                }
            } else {
                #pragma unroll
                for (int c = 0; c < 3; c++) {
                    const float* gf = gb + c * HW + ixf * IMG_D;
                    const float* gc = gb + c * HW + ixc * IMG_D;
                    v00[c] = __ldg(gf + iyf);
                    v01[c] = __ldg(gf + iyc);
                    v10[c] = __ldg(gc + iyf);
                    v11[c] = __ldg(gc + iyc);
                }
            }

            #pragma unroll
            for (int c = 0; c < 3; c++) {
                float sv = w00 * v00[c];
                sv += w10 * v10[c];
                sv += w01 * v01[c];
                sv += w11 * v11[c];
                acc[c][k] += m * sv;
            }
        }
    }

    float* outn = out + (size_t)n * 3 * HW;
    #pragma unroll
    for (int c = 0; c < 3; c++) {
        float* op = outn + c * HW + (r0 + rsub) * IMG_D + col;
        #pragma unroll
        for (int k = 0; k < PXT; k++)
            op[k * ROWSUB * IMG_D] = acc[c][k];
    }
}

extern "C" void kernel_launch(void* const* d_in, const int* in_sizes, int n_in,
                              void* d_out, int out_size)
{
    const float* im1 = (const float*)d_in[0];
    const float* im2 = (const float*)d_in[1];
    const float* C   = (const float*)d_in[2];
    const float* M1  = (const float*)d_in[3];
    const float* M2  = (const float*)d_in[4];
    float* out = (float*)d_out;

    cudaFuncSetAttribute(view_morph5_kernel,
                         cudaFuncAttributeMaxDynamicSharedMemorySize,
                         SMEM_BYTES);

    int blocks = NBATCH * TILES_PER_IMG;  // 1792
    view_morph5_kernel<<<blocks, TPB, SMEM_BYTES>>>(im1, im2, C, M1, M2, out);
}

// round 6
// speedup vs baseline: 2.5008x; 1.1053x over previous
#include <cuda_runtime.h>
#include <cstdint>

#define IMG_D 224
#define HW (IMG_D * IMG_D)
#define NBATCH 64

#define R_TILE 8
#define HALO 4
#define WMAX (R_TILE + 2 * HALO)        // 16 rows staged
#define TILES_PER_IMG (IMG_D / R_TILE)  // 28
#define TPB 448                         // 2 sub-rows x 224 cols
#define ROWSUB (TPB / IMG_D)            // 2
#define PXT (R_TILE / ROWSUB)           // 4 pixels per thread
#define PLANE_W (WMAX * IMG_D)          // 3584 floats per staged plane
#define PLANE_BYTES (PLANE_W * 4)       // 14336 B
#define SMEM_BYTES (6 * PLANE_BYTES)    // 86016 B (dynamic)

// Block = (n, 8-row tile). Stage all 6 channel-plane windows with SIX
// cp.async.bulk (TMA 1D) copies — each window is a contiguous global range
// (full-width rows). Completion via one mbarrier; all threads acquire via
// try_wait. Gathers are conflict-free LDS (row stride 224 == 0 mod 32 banks
// -> bank = column; lanes = distinct columns). Rare out-of-window corner
// (|C|>4 or edge clip, P~6e-5) -> all-global fallback.
__global__ __launch_bounds__(TPB)
void view_morph6_kernel(
    const float* __restrict__ im1,
    const float* __restrict__ im2,
    const float* __restrict__ C,
    const float* __restrict__ M1,
    const float* __restrict__ M2,
    float* __restrict__ out)
{
    extern __shared__ float sp[];                 // 6 planes of PLANE_W floats
    __shared__ alignas(8) uint64_t mbar_storage;

    int blk = blockIdx.x;
    int n = blk / TILES_PER_IMG;
    int tile = blk - n * TILES_PER_IMG;
    int r0 = tile * R_TILE;

    int wl = max(0, r0 - HALO);
    int wh = min(IMG_D - 1, r0 + R_TILE - 1 + HALO);
    int wc = wh - wl + 1;

    int tid = threadIdx.x;
    int col = tid % IMG_D;
    int rsub = tid / IMG_D;

    const float* b1 = im1 + (size_t)n * 3 * HW;
    const float* b2 = im2 + (size_t)n * 3 * HW;

    uint32_t mbar = (uint32_t)__cvta_generic_to_shared(&mbar_storage);
    uint32_t spb0 = (uint32_t)__cvta_generic_to_shared(sp);

    if (tid == 0) {
        asm volatile("mbarrier.init.shared.b64 [%0], 1;"
                     :: "r"(mbar) : "memory");
    }
    __syncthreads();

    if (tid == 0) {
        uint32_t copy_bytes = (uint32_t)(wc * IMG_D * 4);
        asm volatile("mbarrier.arrive.expect_tx.shared.b64 _, [%0], %1;"
                     :: "r"(mbar), "r"(copy_bytes * 6) : "memory");
        #pragma unroll
        for (int pl = 0; pl < 6; pl++) {
            const float* src = (pl < 3 ? b1 + pl * HW : b2 + (pl - 3) * HW)
                               + wl * IMG_D;
            asm volatile(
                "cp.async.bulk.shared::cta.global.mbarrier::complete_tx::bytes"
                " [%0], [%1], %2, [%3];"
                :: "r"(spb0 + pl * PLANE_BYTES), "l"(src),
                   "r"(copy_bytes), "r"(mbar) : "memory");
        }
    }

    // ── prefetch C/M while TMA runs ──
    const float* Cn  = C  + (size_t)n * 2 * HW;
    const float* M1n = M1 + (size_t)n * HW;
    const float* M2n = M2 + (size_t)n * HW;

    float cx[PXT], cy[PXT], m1v[PXT], m2v[PXT];
    #pragma unroll
    for (int k = 0; k < PXT; k++) {
        int r = r0 + rsub + k * ROWSUB;
        int p = r * IMG_D + col;
        cx[k]  = __ldg(Cn + p);
        cy[k]  = __ldg(Cn + HW + p);
        m1v[k] = __ldg(M1n + p);
        m2v[k] = __ldg(M2n + p);
    }

    // ── wait for staged data (acquire) ──
    {
        uint32_t done;
        asm volatile(
            "{\n\t"
            ".reg .pred p;\n\t"
            "mbarrier.try_wait.parity.acquire.cta.shared::cta.b64 p, [%1], 0;\n\t"
            "selp.b32 %0, 1, 0, p;\n\t"
            "}"
            : "=r"(done) : "r"(mbar) : "memory");
        if (!done) {
            asm volatile(
                "{\n\t"
                ".reg .pred P1;\n\t"
                "WL_%=:\n\t"
                "mbarrier.try_wait.parity.acquire.cta.shared::cta.b64 P1, [%0], 0, 0x989680;\n\t"
                "@P1 bra.uni WD_%=;\n\t"
                "bra.uni WL_%=;\n\t"
                "WD_%=:\n\t"
                "}"
                :: "r"(mbar) : "memory");
        }
    }

    float acc[3][PXT];
    #pragma unroll
    for (int c = 0; c < 3; c++)
        #pragma unroll
        for (int k = 0; k < PXT; k++) acc[c][k] = 0.0f;

    #pragma unroll
    for (int k = 0; k < PXT; k++) {
        int r = r0 + rsub + k * ROWSUB;
        float fr = (float)r, fc = (float)col;

        #pragma unroll
        for (int img = 0; img < 2; img++) {
            float s = (img == 0) ? 1.0f : -1.0f;
            float m = (img == 0) ? m1v[k] : m2v[k];
            const float* gb = (img == 0) ? b1 : b2;
            const float* spp = sp + img * 3 * PLANE_W;

            float x = fr + s * cx[k];
            float y = fc + s * cy[k];
            x = fminf(fmaxf(x, 0.001f), (float)IMG_D - 1.001f);
            y = fminf(fmaxf(y, 0.001f), (float)IMG_D - 1.001f);

            int ixf = __float2int_rd(x);
            int ixc = __float2int_ru(x);
            int iyf = __float2int_rd(y);
            int iyc = __float2int_ru(y);

            float wxf = 1.0f - (x - (float)ixf);
            float wxc = 1.0f - ((float)ixc - x);
            float wyf = 1.0f - (y - (float)iyf);
            float wyc = 1.0f - ((float)iyc - y);

            float w00 = wxf * wyf;
            float w10 = wxc * wyf;
            float w01 = wxf * wyc;
            float w11 = wxc * wyc;

            int rf = ixf - wl;
            int rc = ixc - wl;
            bool ok = ((unsigned)rf < (unsigned)wc) &
                      ((unsigned)rc < (unsigned)wc);

            float v00[3], v10[3], v01[3], v11[3];
            if (ok) {
                const float* smf = spp + rf * IMG_D;
                const float* smc = spp + rc * IMG_D;
                #pragma unroll
                for (int c = 0; c < 3; c++) {
                    v00[c] = smf[c * PLANE_W + iyf];
                    v01[c] = smf[c * PLANE_W + iyc];
                    v10[c] = smc[c * PLANE_W + iyf];
                    v11[c] = smc[c * PLANE_W + iyc];
                }
            } else {
                #pragma unroll
                for (int c = 0; c < 3; c++) {
                    const float* gf = gb + c * HW + ixf * IMG_D;
                    const float* gc = gb + c * HW + ixc * IMG_D;
                    v00[c] = __ldg(gf + iyf);
                    v01[c] = __ldg(gf + iyc);
                    v10[c] = __ldg(gc + iyf);
                    v11[c] = __ldg(gc + iyc);
                }
            }

            #pragma unroll
            for (int c = 0; c < 3; c++) {
                float sv = w00 * v00[c];
                sv += w10 * v10[c];
                sv += w01 * v01[c];
                sv += w11 * v11[c];
                acc[c][k] += m * sv;
            }
        }
    }

    float* outn = out + (size_t)n * 3 * HW;
    #pragma unroll
    for (int c = 0; c < 3; c++) {
        float* op = outn + c * HW + (r0 + rsub) * IMG_D + col;
        #pragma unroll
        for (int k = 0; k < PXT; k++)
            op[k * ROWSUB * IMG_D] = acc[c][k];
    }
}

extern "C" void kernel_launch(void* const* d_in, const int* in_sizes, int n_in,
                              void* d_out, int out_size)
{
    const float* im1 = (const float*)d_in[0];
    const float* im2 = (const float*)d_in[1];
    const float* C   = (const float*)d_in[2];
    const float* M1  = (const float*)d_in[3];
    const float* M2  = (const float*)d_in[4];
    float* out = (float*)d_out;

    cudaFuncSetAttribute(view_morph6_kernel,
                         cudaFuncAttributeMaxDynamicSharedMemorySize,
                         SMEM_BYTES);

    int blocks = NBATCH * TILES_PER_IMG;  // 1792
    view_morph6_kernel<<<blocks, TPB, SMEM_BYTES>>>(im1, im2, C, M1, M2, out);
}